// round 15
// baseline (speedup 1.0000x reference)
#include <cuda_runtime.h>
#include <cuda_bf16.h>
#include <cuda_fp16.h>
#include <cstdio>
#include <cstdint>

// Problem constants
#define NB   16
#define TT   512
#define VV   10000
#define DIN  2048
#define DD   1024
#define HH   16
#define LL   4
#define FFD  2048
#define DHD  64
#define ROWS (NB*TT)          // 8192
#define QKVLD (3*DD)          // 3072

// hgemm superstage geometry (BK=64): A 16KB + B 16KB
#define HG2_STAGE 32768
#define HG2_SMEM  (3 * HG2_STAGE)   // 96KB dynamic

// ---------------- device scratch ----------------
__device__ float g_x[ROWS * DD];
__device__ float g_fe[NB * DD];
__device__ float g_fev[LL * NB * DD];
__device__ float g_ztile[LL * NB * 16 * DD];
__device__ float g_z[LL * NB * 16 * DD];

// fp16 side
__device__ __half g_xh[ROWS * DD];
__device__ __half g_qkvh[ROWS * QKVLD];
__device__ __half g_attnh[ROWS * DD];
__device__ __half g_th[ROWS * DD];
__device__ __half g_hh[ROWS * FFD];
__device__ __half g_wqkvh[LL * DD * QKVLD];
__device__ __half g_woh[LL * DD * DD];
__device__ __half g_w1h[LL * DD * FFD];
__device__ __half g_w2h[LL * FFD * DD];
__device__ __half g_wsh[DD * VV];

// ---------------- small helpers ----------------
__device__ __forceinline__ unsigned h2_as_u32(__half2 h) {
    return *(unsigned*)&h;
}
__device__ __forceinline__ uint32_t smem_u32(const void* p) {
    uint32_t a;
    asm("{ .reg .u64 t; cvta.to.shared.u64 t, %1; cvt.u32.u64 %0, t; }"
        : "=r"(a) : "l"(p));
    return a;
}

#define CPA16(dst, src) \
    asm volatile("cp.async.cg.shared.global [%0], [%1], 16;" :: "r"(dst), "l"(src))
#define CPA16Z(dst, src, sz) \
    asm volatile("cp.async.cg.shared.global [%0], [%1], 16, %2;" :: "r"(dst), "l"(src), "r"(sz))
#define CPA_COMMIT() asm volatile("cp.async.commit_group;" ::: "memory")
#define CPA_WAIT1()  asm volatile("cp.async.wait_group 1;" ::: "memory")

#define LDSM4(r0, r1, r2, r3, addr) \
    asm volatile("ldmatrix.sync.aligned.m8n8.x4.shared.b16 {%0,%1,%2,%3}, [%4];" \
                 : "=r"(r0), "=r"(r1), "=r"(r2), "=r"(r3) : "r"(addr))
#define LDSM4T(r0, r1, r2, r3, addr) \
    asm volatile("ldmatrix.sync.aligned.m8n8.x4.trans.shared.b16 {%0,%1,%2,%3}, [%4];" \
                 : "=r"(r0), "=r"(r1), "=r"(r2), "=r"(r3) : "r"(addr))

#define MMA16816(acc, a0, a1, a2, a3, b0, b1) \
    asm volatile( \
        "mma.sync.aligned.m16n8k16.row.col.f32.f16.f16.f32 " \
        "{%0,%1,%2,%3}, {%4,%5,%6,%7}, {%8,%9}, {%0,%1,%2,%3};" \
        : "+f"((acc)[0]), "+f"((acc)[1]), "+f"((acc)[2]), "+f"((acc)[3]) \
        : "r"(a0), "r"(a1), "r"(a2), "r"(a3), "r"(b0), "r"(b1))

// ---------------- f32 -> f16 conversion (n % 4 == 0) ----------------
__global__ void f2h_kernel(const float* __restrict__ src, __half* __restrict__ dst, int n)
{
    int i = (blockIdx.x * blockDim.x + threadIdx.x) * 4;
    if (i < n) {
        float4 v = *(const float4*)(src + i);
        uint2 o;
        o.x = h2_as_u32(__floats2half2_rn(v.x, v.y));
        o.y = h2_as_u32(__floats2half2_rn(v.z, v.w));
        *(uint2*)(dst + i) = o;
    }
}

// pack Wq|Wk|Wv -> [l][k][3*DD] fp16.
__global__ void f2h3_kernel(const float* __restrict__ wq, const float* __restrict__ wk,
                            const float* __restrict__ wv, __half* __restrict__ dst)
{
    const int sel = blockIdx.y;
    const float* src = (sel == 0) ? wq : (sel == 1) ? wk : wv;
    int i = (blockIdx.x * blockDim.x + threadIdx.x) * 4;
    if (i < LL * DD * DD) {
        float4 v = *(const float4*)(src + i);
        const int lk = i >> 10;
        const int j  = i & (DD - 1);
        __half* d = dst + (size_t)lk * QKVLD + sel * DD + j;
        uint2 o;
        o.x = h2_as_u32(__floats2half2_rn(v.x, v.y));
        o.y = h2_as_u32(__floats2half2_rn(v.z, v.w));
        *(uint2*)d = o;
    }
}

// ==== fp16 GEMM: 128x128 CTA tile, 4 warps (2x2, 64x64), BK=64, 3 stages ==
// C = A(MxK)*B(KxN) [+bias][ReLU]. fp16 in. M%128==0, K%64==0, Nn%8==0.
// A smem (16KB/stage): 128 rows x 8 units(16B); phys = r*8 + (u ^ (r&7))
// B smem (16KB/stage, +16384): 64 k-rows x 16 n-units; phys = kr*16 + (nu ^ (kr&7))
template<bool RELU, bool BIAS, bool HOUT>
__global__ __launch_bounds__(128, 2) void hgemm(
    const __half* __restrict__ A, const __half* __restrict__ B,
    const float* __restrict__ bias, void* __restrict__ Cv,
    int M, int Nn, int K)
{
    extern __shared__ __align__(16) unsigned char sm[];

    const int tid  = threadIdx.x;
    const int lane = tid & 31;
    const int warp = tid >> 5;
    const int row0 = blockIdx.y * 128;
    const int col0 = blockIdx.x * 128;
    const int wm = (warp >> 1) * 64;
    const int wn = (warp & 1) * 64;
    const int g  = lane >> 2;
    const int tq = lane & 3;

    const uint32_t sbase = smem_u32(sm);

    // consumer lane components
    const int g8 = lane >> 3, li = lane & 7;
    const int rowa = wm + (g8 & 1) * 8 + li;
    const int sa3 = rowa & 7;
    const int ub = g8 >> 1;
    const uint32_t aBase = (uint32_t)rowa * 128;
    const int krb = (g8 & 1) * 8 + li;          // row within 16-row k-subchunk
    const int sb = krb & 7;
    const int nub = (wn >> 3) + (g8 >> 1);
    uint32_t nOff[4];
#pragma unroll
    for (int jp = 0; jp < 4; jp++)
        nOff[jp] = ((unsigned)((nub + 2 * jp) ^ sb) << 4);
    const uint32_t bBase = 16384u + (uint32_t)krb * 256;

    float acc[4][8][4];
#pragma unroll
    for (int i = 0; i < 4; i++)
#pragma unroll
        for (int j = 0; j < 8; j++)
#pragma unroll
            for (int c = 0; c < 4; c++) acc[i][j][c] = 0.f;

    const int nk = K >> 6;   // 64-K superstages (>=16 for all our shapes)

    auto issue = [&](int c, int st) {
        const int k0 = c * 64;
        const uint32_t stb = sbase + (uint32_t)st * HG2_STAGE;
#pragma unroll
        for (int i = 0; i < 8; i++) {
            const int ul = tid + 128 * i;
            const int r = ul >> 3, u = ul & 7;
            const int phys = r * 8 + (u ^ (r & 7));
            CPA16(stb + (uint32_t)phys * 16,
                  A + (size_t)(row0 + r) * K + k0 + u * 8);
        }
#pragma unroll
        for (int i = 0; i < 8; i++) {
            const int ul = tid + 128 * i;
            const int kr = ul >> 4, nu = ul & 15;
            const int phys = kr * 16 + (nu ^ (kr & 7));
            const int gc = col0 + nu * 8;
            const unsigned sz = (gc + 7 < Nn) ? 16u : 0u;
            CPA16Z(stb + 16384u + (uint32_t)phys * 16,
                   B + (size_t)(k0 + kr) * Nn + (sz ? gc : 0), sz);
        }
        CPA_COMMIT();
    };

    issue(0, 0);
    issue(1, 1);

    for (int it = 0; it < nk; it++) {
        const int st = it % 3;
        CPA_WAIT1();
        __syncthreads();
        if (it + 2 < nk) issue(it + 2, (it + 2) % 3);
        else CPA_COMMIT();

        const uint32_t stb = sbase + (uint32_t)st * HG2_STAGE;
#pragma unroll
        for (int kk = 0; kk < 4; kk++) {
            unsigned af[4][4], bf[8][2];
            const int u = 2 * kk + ub;
            const uint32_t aO = aBase + ((unsigned)(u ^ sa3) << 4);
#pragma unroll
            for (int i = 0; i < 4; i++)
                LDSM4(af[i][0], af[i][1], af[i][2], af[i][3],
                      stb + aO + (uint32_t)i * 2048);
            const uint32_t bO = bBase + (uint32_t)kk * 4096;
#pragma unroll
            for (int jp = 0; jp < 4; jp++) {
                unsigned t0, t1, t2, t3;
                LDSM4T(t0, t1, t2, t3, stb + bO + nOff[jp]);
                bf[2 * jp][0] = t0; bf[2 * jp][1] = t1;
                bf[2 * jp + 1][0] = t2; bf[2 * jp + 1][1] = t3;
            }
#pragma unroll
            for (int i = 0; i < 4; i++)
#pragma unroll
                for (int j = 0; j < 8; j++)
                    MMA16816(acc[i][j], af[i][0], af[i][1], af[i][2], af[i][3],
                             bf[j][0], bf[j][1]);
        }
    }

#pragma unroll
    for (int i = 0; i < 4; i++) {
        const int r0r = row0 + wm + i * 16 + g;
#pragma unroll
        for (int j = 0; j < 8; j++) {
            const int col = col0 + wn + j * 8 + tq * 2;
            if (col >= Nn) continue;
            float2 bsv = make_float2(0.f, 0.f);
            if (BIAS) bsv = *(const float2*)(bias + col);
            float2 v0, v1;
            v0.x = acc[i][j][0] + (BIAS ? bsv.x : 0.f);
            v0.y = acc[i][j][1] + (BIAS ? bsv.y : 0.f);
            v1.x = acc[i][j][2] + (BIAS ? bsv.x : 0.f);
            v1.y = acc[i][j][3] + (BIAS ? bsv.y : 0.f);
            if (RELU) {
                v0.x = fmaxf(v0.x, 0.f); v0.y = fmaxf(v0.y, 0.f);
                v1.x = fmaxf(v1.x, 0.f); v1.y = fmaxf(v1.y, 0.f);
            }
            if (HOUT) {
                __half* C = (__half*)Cv;
                *(unsigned*)(C + (size_t)r0r * Nn + col)       = h2_as_u32(__floats2half2_rn(v0.x, v0.y));
                *(unsigned*)(C + (size_t)(r0r + 8) * Nn + col) = h2_as_u32(__floats2half2_rn(v1.x, v1.y));
            } else {
                float* C = (float*)Cv;
                *(float2*)(C + (size_t)r0r * Nn + col) = v0;
                *(float2*)(C + (size_t)(r0r + 8) * Nn + col) = v1;
            }
        }
    }
}

// ---------------- SIMT SGEMM (small M cases only) -------------------------
#define BM 128
#define BN 128
#define BK 8
#define TM 8
#define TN 8

template<bool RELU, bool BIAS>
__global__ void sgemm(const float* __restrict__ A, const float* __restrict__ B,
                      const float* __restrict__ bias, float* __restrict__ C,
                      int M, int Nn, int K)
{
    __shared__ float As[BK][BM];
    __shared__ float Bs[BK][BN];
    const int tid = threadIdx.x;
    const int row0 = blockIdx.y * BM;
    const int col0 = blockIdx.x * BN;
    const int tx = tid % 16;
    const int ty = tid / 16;

    float acc[TM][TN];
#pragma unroll
    for (int i = 0; i < TM; i++)
#pragma unroll
        for (int j = 0; j < TN; j++) acc[i][j] = 0.f;

    const int aRow = tid >> 1;
    const int aCol = (tid & 1) * 4;
    const int bRow = tid >> 5;
    const int bCol = (tid & 31) * 4;

    for (int k0 = 0; k0 < K; k0 += BK) {
        int gr = row0 + aRow;
        float4 av = make_float4(0.f, 0.f, 0.f, 0.f);
        if (gr < M) av = *(const float4*)(A + (size_t)gr * K + k0 + aCol);
        As[aCol + 0][aRow] = av.x;
        As[aCol + 1][aRow] = av.y;
        As[aCol + 2][aRow] = av.z;
        As[aCol + 3][aRow] = av.w;

        int gc = col0 + bCol;
        float4 bv = make_float4(0.f, 0.f, 0.f, 0.f);
        if (gc < Nn) bv = *(const float4*)(B + (size_t)(k0 + bRow) * Nn + gc);
        *(float4*)&Bs[bRow][bCol] = bv;
        __syncthreads();

#pragma unroll
        for (int kk = 0; kk < BK; kk++) {
            float ar[TM], br[TN];
#pragma unroll
            for (int i = 0; i < TM; i++) ar[i] = As[kk][ty * TM + i];
#pragma unroll
            for (int j = 0; j < TN; j++) br[j] = Bs[kk][tx * TN + j];
#pragma unroll
            for (int i = 0; i < TM; i++)
#pragma unroll
                for (int j = 0; j < TN; j++)
                    acc[i][j] = fmaf(ar[i], br[j], acc[i][j]);
        }
        __syncthreads();
    }

#pragma unroll
    for (int i = 0; i < TM; i++) {
        int r = row0 + ty * TM + i;
        if (r >= M) continue;
#pragma unroll
        for (int j = 0; j < TN; j++) {
            int c = col0 + tx * TN + j;
            if (c >= Nn) continue;
            float v = acc[i][j];
            if (BIAS) v += bias[c];
            if (RELU) v = fmaxf(v, 0.f);
            C[(size_t)r * Nn + c] = v;
        }
    }
}

template<bool BIAS>
__global__ void sgemm_bz(const float* __restrict__ A0, const float* __restrict__ B0,
                         const float* __restrict__ bias0, float* __restrict__ C0,
                         int M, int Nn, int K,
                         size_t sA, size_t sB, size_t sBias, size_t sC)
{
    const int z = blockIdx.z;
    const float* A = A0 + sA * z;
    const float* B = B0 + sB * z;
    const float* bias = BIAS ? (bias0 + sBias * z) : nullptr;
    float* C = C0 + sC * z;

    __shared__ float As[BK][BM];
    __shared__ float Bs[BK][BN];
    const int tid = threadIdx.x;
    const int row0 = blockIdx.y * BM;
    const int col0 = blockIdx.x * BN;
    const int tx = tid % 16;
    const int ty = tid / 16;

    float acc[TM][TN];
#pragma unroll
    for (int i = 0; i < TM; i++)
#pragma unroll
        for (int j = 0; j < TN; j++) acc[i][j] = 0.f;

    const int aRow = tid >> 1;
    const int aCol = (tid & 1) * 4;
    const int bRow = tid >> 5;
    const int bCol = (tid & 31) * 4;

    for (int k0 = 0; k0 < K; k0 += BK) {
        int gr = row0 + aRow;
        float4 av = make_float4(0.f, 0.f, 0.f, 0.f);
        if (gr < M) av = *(const float4*)(A + (size_t)gr * K + k0 + aCol);
        As[aCol + 0][aRow] = av.x;
        As[aCol + 1][aRow] = av.y;
        As[aCol + 2][aRow] = av.z;
        As[aCol + 3][aRow] = av.w;

        int gc = col0 + bCol;
        float4 bv = make_float4(0.f, 0.f, 0.f, 0.f);
        if (gc < Nn) bv = *(const float4*)(B + (size_t)(k0 + bRow) * Nn + gc);
        *(float4*)&Bs[bRow][bCol] = bv;
        __syncthreads();

#pragma unroll
        for (int kk = 0; kk < BK; kk++) {
            float ar[TM], br[TN];
#pragma unroll
            for (int i = 0; i < TM; i++) ar[i] = As[kk][ty * TM + i];
#pragma unroll
            for (int j = 0; j < TN; j++) br[j] = Bs[kk][tx * TN + j];
#pragma unroll
            for (int i = 0; i < TM; i++)
#pragma unroll
                for (int j = 0; j < TN; j++)
                    acc[i][j] = fmaf(ar[i], br[j], acc[i][j]);
        }
        __syncthreads();
    }

#pragma unroll
    for (int i = 0; i < TM; i++) {
        int r = row0 + ty * TM + i;
        if (r >= M) continue;
#pragma unroll
        for (int j = 0; j < TN; j++) {
            int c = col0 + tx * TN + j;
            if (c >= Nn) continue;
            float v = acc[i][j];
            if (BIAS) v += bias[c];
            C[(size_t)r * Nn + c] = v;
        }
    }
}

// ---------------- embedding (dual write f32 + f16) ------------
__global__ void embed_kernel(const int* __restrict__ cap, const float* __restrict__ emb,
                             const float* __restrict__ pos, float* __restrict__ X,
                             __half* __restrict__ Xh)
{
    int r = blockIdx.x;
    int t = r & (TT - 1);
    int c = cap[r];
    int d = threadIdx.x * 4;
    float4 e = *(const float4*)(emb + (size_t)c * DD + d);
    float4 p = *(const float4*)(pos + (size_t)t * DD + d);
    e.x += p.x; e.y += p.y; e.z += p.z; e.w += p.w;
    *(float4*)(X + (size_t)r * DD + d) = e;
    uint2 hv;
    hv.x = h2_as_u32(__floats2half2_rn(e.x, e.y));
    hv.y = h2_as_u32(__floats2half2_rn(e.z, e.w));
    *(uint2*)(Xh + (size_t)r * DD + d) = hv;
}

// ============ tensor-core flash attention (packed QKV input) ==============
__global__ __launch_bounds__(128) void flash_attn2(
    const __half* __restrict__ Q, const __half* __restrict__ K,
    const __half* __restrict__ V, __half* __restrict__ O)
{
    __shared__ __align__(16) unsigned char sQ[8192];
    __shared__ __align__(16) unsigned char sKV[2][16384];

    const int bid = blockIdx.x;
    const int qt = bid & 7;
    const int h  = (bid >> 3) & 15;
    const int n  = bid >> 7;
    const int q0 = qt * 64;

    const int tid = threadIdx.x;
    const int lane = tid & 31;
    const int warp = tid >> 5;
    const int g8 = lane >> 3, li = lane & 7;
    const int g = lane >> 2, tq = lane & 3;

    const uint32_t sQb = smem_u32(sQ);
    const uint32_t sKVb = smem_u32(sKV);

#pragma unroll
    for (int i = 0; i < 4; i++) {
        const int ui = tid + 128 * i;
        const int r = ui >> 3, u = ui & 7;
        const int phys = r * 8 + (u ^ (r & 7));
        CPA16(sQb + phys * 16,
              Q + ((size_t)(n * TT + q0 + r)) * QKVLD + h * DHD + u * 8);
    }
    CPA_COMMIT();

    auto load_kv = [&](int t, int buf) {
        const int j0 = t * 64;
        const uint32_t base = sKVb + (uint32_t)buf * 16384;
#pragma unroll
        for (int i = 0; i < 4; i++) {
            const int ui = tid + 128 * i;
            const int r = ui >> 3, u = ui & 7;
            const int phys = r * 8 + (u ^ (r & 7));
            const size_t go = ((size_t)(n * TT + j0 + r)) * QKVLD + h * DHD + u * 8;
            CPA16(base + phys * 16, K + go);
            CPA16(base + 8192u + phys * 16, V + go);
        }
        CPA_COMMIT();
    };

    load_kv(0, 0);
    CPA_WAIT1();
    __syncthreads();

    unsigned qa[4][4];
    {
        const int qrow = 16 * warp + (g8 & 1) * 8 + li;
#pragma unroll
        for (int kc = 0; kc < 4; kc++) {
            const int u = 2 * kc + (g8 >> 1);
            LDSM4(qa[kc][0], qa[kc][1], qa[kc][2], qa[kc][3],
                  sQb + (uint32_t)(qrow * 8 + (u ^ (qrow & 7))) * 16);
        }
    }

    float o[8][4];
#pragma unroll
    for (int j = 0; j < 8; j++)
#pragma unroll
        for (int c = 0; c < 4; c++) o[j][c] = 0.f;
    float m0 = -1e30f, m1 = -1e30f, l0 = 0.f, l1 = 0.f;

    const int r0q = q0 + 16 * warp + g;
    const int nt = qt + 1;

    const int kbrow = (g8 >> 1) * 8 + li;
    const int vrow  = (g8 & 1) * 8 + li;

    for (int t = 0; t < nt; t++) {
        const int buf = t & 1;
        __syncthreads();
        if (t + 1 < nt) load_kv(t + 1, buf ^ 1);
        else CPA_COMMIT();
        CPA_WAIT1();
        __syncthreads();

        const uint32_t kb = sKVb + (uint32_t)buf * 16384;
        const uint32_t vb = kb + 8192u;

        float s[8][4];
#pragma unroll
        for (int j = 0; j < 8; j++)
#pragma unroll
            for (int c = 0; c < 4; c++) s[j][c] = 0.f;

#pragma unroll
        for (int kc = 0; kc < 4; kc++) {
            const int ku = 2 * kc + (g8 & 1);
#pragma unroll
            for (int jp = 0; jp < 4; jp++) {
                const int row = 16 * jp + kbrow;
                unsigned t0, t1, t2, t3;
                LDSM4(t0, t1, t2, t3,
                      kb + (uint32_t)(row * 8 + (ku ^ (row & 7))) * 16);
                MMA16816(s[2 * jp],     qa[kc][0], qa[kc][1], qa[kc][2], qa[kc][3], t0, t1);
                MMA16816(s[2 * jp + 1], qa[kc][0], qa[kc][1], qa[kc][2], qa[kc][3], t2, t3);
            }
        }

        const int j0 = t * 64;
        float mx0 = -1e30f, mx1 = -1e30f;
        if (t == qt) {
#pragma unroll
            for (int j = 0; j < 8; j++) {
                const int col = j0 + 8 * j + 2 * tq;
                s[j][0] = (col     <= r0q)     ? s[j][0] * 0.125f : -1e30f;
                s[j][1] = (col + 1 <= r0q)     ? s[j][1] * 0.125f : -1e30f;
                s[j][2] = (col     <= r0q + 8) ? s[j][2] * 0.125f : -1e30f;
                s[j][3] = (col + 1 <= r0q + 8) ? s[j][3] * 0.125f : -1e30f;
                mx0 = fmaxf(mx0, fmaxf(s[j][0], s[j][1]));
                mx1 = fmaxf(mx1, fmaxf(s[j][2], s[j][3]));
            }
        } else {
#pragma unroll
            for (int j = 0; j < 8; j++) {
                s[j][0] *= 0.125f; s[j][1] *= 0.125f;
                s[j][2] *= 0.125f; s[j][3] *= 0.125f;
                mx0 = fmaxf(mx0, fmaxf(s[j][0], s[j][1]));
                mx1 = fmaxf(mx1, fmaxf(s[j][2], s[j][3]));
            }
        }
        mx0 = fmaxf(mx0, __shfl_xor_sync(0xffffffffu, mx0, 1));
        mx0 = fmaxf(mx0, __shfl_xor_sync(0xffffffffu, mx0, 2));
        mx1 = fmaxf(mx1, __shfl_xor_sync(0xffffffffu, mx1, 1));
        mx1 = fmaxf(mx1, __shfl_xor_sync(0xffffffffu, mx1, 2));

        const float mn0 = fmaxf(m0, mx0);
        const float mn1 = fmaxf(m1, mx1);
        const float sc0 = __expf(m0 - mn0);
        const float sc1 = __expf(m1 - mn1);
        m0 = mn0; m1 = mn1;
        l0 *= sc0; l1 *= sc1;
#pragma unroll
        for (int j = 0; j < 8; j++) {
            o[j][0] *= sc0; o[j][1] *= sc0;
            o[j][2] *= sc1; o[j][3] *= sc1;
        }

        unsigned pa[8], pb[8];
#pragma unroll
        for (int j = 0; j < 8; j++) {
            const float p0 = __expf(s[j][0] - mn0);
            const float p1 = __expf(s[j][1] - mn0);
            const float p2 = __expf(s[j][2] - mn1);
            const float p3 = __expf(s[j][3] - mn1);
            l0 += p0 + p1; l1 += p2 + p3;
            pa[j] = h2_as_u32(__floats2half2_rn(p0, p1));
            pb[j] = h2_as_u32(__floats2half2_rn(p2, p3));
        }

#pragma unroll
        for (int kc = 0; kc < 4; kc++) {
#pragma unroll
            for (int jp = 0; jp < 4; jp++) {
                const int row = 16 * kc + vrow;
                const int u = 2 * jp + (g8 >> 1);
                unsigned t0, t1, t2, t3;
                LDSM4T(t0, t1, t2, t3,
                       vb + (uint32_t)(row * 8 + (u ^ (row & 7))) * 16);
                MMA16816(o[2 * jp],     pa[2 * kc], pb[2 * kc], pa[2 * kc + 1], pb[2 * kc + 1], t0, t1);
                MMA16816(o[2 * jp + 1], pa[2 * kc], pb[2 * kc], pa[2 * kc + 1], pb[2 * kc + 1], t2, t3);
            }
        }
    }

    l0 += __shfl_xor_sync(0xffffffffu, l0, 1);
    l0 += __shfl_xor_sync(0xffffffffu, l0, 2);
    l1 += __shfl_xor_sync(0xffffffffu, l1, 1);
    l1 += __shfl_xor_sync(0xffffffffu, l1, 2);
    const float inv0 = 1.f / l0;
    const float inv1 = 1.f / l1;

    const size_t obase = ((size_t)((n * HH + h) * TT + q0 + 16 * warp)) * DHD;
#pragma unroll
    for (int j = 0; j < 8; j++) {
        const int col = 8 * j + 2 * tq;
        *(unsigned*)(O + obase + (size_t)g * DHD + col) =
            h2_as_u32(__floats2half2_rn(o[j][0] * inv0, o[j][1] * inv0));
        *(unsigned*)(O + obase + (size_t)(g + 8) * DHD + col) =
            h2_as_u32(__floats2half2_rn(o[j][2] * inv1, o[j][3] * inv1));
    }
}

// ---------------- residual + LayerNorm (fp16 delta, dual write) ----------
template<bool FOUT>
__global__ void ln_kernel(const float* __restrict__ X, const __half* __restrict__ Dd,
                          const float* __restrict__ g, const float* __restrict__ b,
                          float* __restrict__ out, __half* __restrict__ outh)
{
    const int r = blockIdx.x;
    const int tid = threadIdx.x;
    const float* xr = X + (size_t)r * DD;
    const __half* dr = Dd + (size_t)r * DD;
    const int d = tid * 4;
    float4 xv = *(const float4*)(xr + d);
    uint2 du = *(const uint2*)(dr + d);
    float2 d0 = __half22float2(*(__half2*)&du.x);
    float2 d1 = __half22float2(*(__half2*)&du.y);
    float v0 = xv.x + d0.x, v1 = xv.y + d0.y, v2 = xv.z + d1.x, v3 = xv.w + d1.y;

    __shared__ float s1[256], s2[256];
    s1[tid] = v0 + v1 + v2 + v3;
    s2[tid] = v0 * v0 + v1 * v1 + v2 * v2 + v3 * v3;
    __syncthreads();
    for (int st = 128; st > 0; st >>= 1) {
        if (tid < st) { s1[tid] += s1[tid + st]; s2[tid] += s2[tid + st]; }
        __syncthreads();
    }
    const float mean = s1[0] * (1.f / DD);
    const float var = s2[0] * (1.f / DD) - mean * mean;
    const float rstd = rsqrtf(var + 1e-5f);

    float4 ov;
    ov.x = g[d + 0] * (v0 - mean) * rstd + b[d + 0];
    ov.y = g[d + 1] * (v1 - mean) * rstd + b[d + 1];
    ov.z = g[d + 2] * (v2 - mean) * rstd + b[d + 2];
    ov.w = g[d + 3] * (v3 - mean) * rstd + b[d + 3];
    if (FOUT) *(float4*)(out + (size_t)r * DD + d) = ov;
    uint2 hv;
    hv.x = h2_as_u32(__floats2half2_rn(ov.x, ov.y));
    hv.y = h2_as_u32(__floats2half2_rn(ov.z, ov.w));
    *(uint2*)(outh + (size_t)r * DD + d) = hv;
}

// ---- fused: LN(x + attn_delta) then LN(o1 + z_broadcast) ----------------
__global__ void ln_fused2(const float* __restrict__ X, const __half* __restrict__ Dd,
                          const float* __restrict__ g1, const float* __restrict__ b1,
                          const float* __restrict__ Z,
                          const float* __restrict__ g2, const float* __restrict__ b2,
                          float* __restrict__ out, __half* __restrict__ outh)
{
    const int r = blockIdx.x;
    const int tid = threadIdx.x;
    const int d = tid * 4;
    __shared__ float s1[256], s2[256];

    float4 xv = *(const float4*)(X + (size_t)r * DD + d);
    uint2 du = *(const uint2*)(Dd + (size_t)r * DD + d);
    float2 d0 = __half22float2(*(__half2*)&du.x);
    float2 d1 = __half22float2(*(__half2*)&du.y);
    float v0 = xv.x + d0.x, v1 = xv.y + d0.y, v2 = xv.z + d1.x, v3 = xv.w + d1.y;

    s1[tid] = v0 + v1 + v2 + v3;
    s2[tid] = v0 * v0 + v1 * v1 + v2 * v2 + v3 * v3;
    __syncthreads();
    for (int st = 128; st > 0; st >>= 1) {
        if (tid < st) { s1[tid] += s1[tid + st]; s2[tid] += s2[tid + st]; }
        __syncthreads();
    }
    float mean = s1[0] * (1.f / DD);
    float var = s2[0] * (1.f / DD) - mean * mean;
    float rstd = rsqrtf(var + 1e-5f);

    float o0 = g1[d + 0] * (v0 - mean) * rstd + b1[d + 0];
    float o1_ = g1[d + 1] * (v1 - mean) * rstd + b1[d + 1];
    float o2_ = g1[d + 2] * (v2 - mean) * rstd + b1[d + 2];
    float o3 = g1[d + 3] * (v3 - mean) * rstd + b1[d + 3];

    const int n = r >> 9;
    const int s = r & (TT - 1);
    const size_t zr = (size_t)(n * 16 + (s >> 5));
    float4 zv = *(const float4*)(Z + zr * DD + d);
    v0 = o0 + zv.x; v1 = o1_ + zv.y; v2 = o2_ + zv.z; v3 = o3 + zv.w;

    __syncthreads();
    s1[tid] = v0 + v1 + v2 + v3;
    s2[tid] = v0 * v0 + v1 * v1 + v2 * v2 + v3 * v3;
    __syncthreads();
    for (int st = 128; st > 0; st >>= 1) {
        if (tid < st) { s1[tid] += s1[tid + st]; s2[tid] += s2[tid + st]; }
        __syncthreads();
    }
    mean = s1[0] * (1.f / DD);
    var = s2[0] * (1.f / DD) - mean * mean;
    rstd = rsqrtf(var + 1e-5f);

    float4 ov;
    ov.x = g2[d + 0] * (v0 - mean) * rstd + b2[d + 0];
    ov.y = g2[d + 1] * (v1 - mean) * rstd + b2[d + 1];
    ov.z = g2[d + 2] * (v2 - mean) * rstd + b2[d + 2];
    ov.w = g2[d + 3] * (v3 - mean) * rstd + b2[d + 3];
    *(float4*)(out + (size_t)r * DD + d) = ov;
    uint2 hv;
    hv.x = h2_as_u32(__floats2half2_rn(ov.x, ov.y));
    hv.y = h2_as_u32(__floats2half2_rn(ov.z, ov.w));
    *(uint2*)(outh + (size_t)r * DD + d) = hv;
}

// ------------- tiled rows for cross-attn out-projection (batched) --------
__global__ void tilefe_kernel(const float* __restrict__ fev, float* __restrict__ A)
{
    const int bx = blockIdx.x;
    const int z = bx >> 8;
    const int rl = bx & 255;
    const int n = rl >> 4;
    const int g = rl & 15;
    const int d = threadIdx.x * 4;
    const float* src = fev + (size_t)z * NB * DD + (size_t)n * DD + g * 64;
    float4 v = *(const float4*)(src + (d & 63));
    *(float4*)(A + (size_t)z * NB * 16 * DD + (size_t)rl * DD + d) = v;
}

// ---------------- launch --------------------------------------------------
extern "C" void kernel_launch(void* const* d_in, const int* in_sizes, int n_in,
                              void* d_out, int out_size)
{
    const float* features = (const float*)d_in[0];
    const int*   captions = (const int*)d_in[1];
    const float* feat_W   = (const float*)d_in[2];
    const float* feat_b   = (const float*)d_in[3];
    const float* cap_emb  = (const float*)d_in[4];
    const float* pos_emb  = (const float*)d_in[5];
    const float* sa_Wq = (const float*)d_in[6];
    const float* sa_Wk = (const float*)d_in[7];
    const float* sa_Wv = (const float*)d_in[8];
    const float* sa_Wo = (const float*)d_in[9];
    const float* sa_bo = (const float*)d_in[10];
    const float* sa_g  = (const float*)d_in[11];
    const float* sa_b  = (const float*)d_in[12];
    const float* ca_Wv = (const float*)d_in[15];
    const float* ca_Wo = (const float*)d_in[16];
    const float* ca_bo = (const float*)d_in[17];
    const float* ca_g  = (const float*)d_in[18];
    const float* ca_b  = (const float*)d_in[19];
    const float* ff_W1 = (const float*)d_in[20];
    const float* ff_b1 = (const float*)d_in[21];
    const float* ff_W2 = (const float*)d_in[22];
    const float* ff_b2 = (const float*)d_in[23];
    const float* ff_g  = (const float*)d_in[24];
    const float* ff_b  = (const float*)d_in[25];
    const float* score_W = (const float*)d_in[26];
    const float* score_b = (const float*)d_in[27];
    float* out = (float*)d_out;

    float *px, *pfe, *pfev, *pzt, *pz;
    __half *pxh, *pqkvh, *pattnh, *pth, *phh;
    __half *pwqkvh, *pwoh, *pw1h, *pw2h, *pwsh;
    cudaGetSymbolAddress((void**)&px,    g_x);
    cudaGetSymbolAddress((void**)&pfe,   g_fe);
    cudaGetSymbolAddress((void**)&pfev,  g_fev);
    cudaGetSymbolAddress((void**)&pzt,   g_ztile);
    cudaGetSymbolAddress((void**)&pz,    g_z);
    cudaGetSymbolAddress((void**)&pxh,    g_xh);
    cudaGetSymbolAddress((void**)&pqkvh,  g_qkvh);
    cudaGetSymbolAddress((void**)&pattnh, g_attnh);
    cudaGetSymbolAddress((void**)&pth,    g_th);
    cudaGetSymbolAddress((void**)&phh,    g_hh);
    cudaGetSymbolAddress((void**)&pwqkvh, g_wqkvh);
    cudaGetSymbolAddress((void**)&pwoh,   g_woh);
    cudaGetSymbolAddress((void**)&pw1h,   g_w1h);
    cudaGetSymbolAddress((void**)&pw2h,   g_w2h);
    cudaGetSymbolAddress((void**)&pwsh,   g_wsh);

    // side stream + events + func attrs (created once; first call is eager)
    static cudaStream_t s2 = nullptr;
    static cudaEvent_t ev_fork = nullptr, ev_wqkv = nullptr, ev_rest = nullptr;
    if (!s2) {
        cudaStreamCreateWithFlags(&s2, cudaStreamNonBlocking);
        cudaEventCreateWithFlags(&ev_fork, cudaEventDisableTiming);
        cudaEventCreateWithFlags(&ev_wqkv, cudaEventDisableTiming);
        cudaEventCreateWithFlags(&ev_rest, cudaEventDisableTiming);
        cudaFuncSetAttribute(hgemm<false, false, true>, cudaFuncAttributeMaxDynamicSharedMemorySize, HG2_SMEM);
        cudaFuncSetAttribute(hgemm<false, true, true>,  cudaFuncAttributeMaxDynamicSharedMemorySize, HG2_SMEM);
        cudaFuncSetAttribute(hgemm<true, true, true>,   cudaFuncAttributeMaxDynamicSharedMemorySize, HG2_SMEM);
        cudaFuncSetAttribute(hgemm<false, true, false>, cudaFuncAttributeMaxDynamicSharedMemorySize, HG2_SMEM);
    }

    const int tb = 256;
    const int nDD = LL * DD * DD;
    const int nFF = LL * DD * FFD;
    const int nS = DD * VV;

    const dim3 gP(DD / 128, ROWS / 128);        // 8 x 64
    const dim3 gQKV(QKVLD / 128, ROWS / 128);   // 24 x 64
    const dim3 gF(FFD / 128, ROWS / 128);       // 16 x 64

    // ---- fork: prologue on side stream -------------------------------
    cudaEventRecord(ev_fork, 0);
    cudaStreamWaitEvent(s2, ev_fork, 0);

    f2h3_kernel<<<dim3(nDD / 4 / tb, 3), tb, 0, s2>>>(sa_Wq, sa_Wk, sa_Wv, pwqkvh);
    cudaEventRecord(ev_wqkv, s2);
    f2h_kernel<<<(nDD / 4 + tb - 1) / tb, tb, 0, s2>>>(sa_Wo, pwoh, nDD);
    f2h_kernel<<<(nFF / 4 + tb - 1) / tb, tb, 0, s2>>>(ff_W1, pw1h, nFF);
    f2h_kernel<<<(nFF / 4 + tb - 1) / tb, tb, 0, s2>>>(ff_W2, pw2h, nFF);
    f2h_kernel<<<(nS / 4 + tb - 1) / tb, tb, 0, s2>>>(score_W, pwsh, nS);
    sgemm<false, true><<<dim3(DD / BN, 1), 256, 0, s2>>>(features, feat_W, feat_b, pfe, NB, DD, DIN);
    sgemm_bz<false><<<dim3(DD / BN, 1, LL), 256, 0, s2>>>(pfe, ca_Wv, nullptr, pfev,
                                                          NB, DD, DD,
                                                          0, (size_t)DD * DD, 0, (size_t)NB * DD);
    tilefe_kernel<<<LL * NB * 16, 256, 0, s2>>>(pfev, pzt);
    sgemm_bz<true><<<dim3(DD / BN, 2, LL), 256, 0, s2>>>(pzt, ca_Wo, ca_bo, pz,
                                                         NB * 16, DD, DD,
                                                         (size_t)NB * 16 * DD, (size_t)DD * DD,
                                                         DD, (size_t)NB * 16 * DD);
    cudaEventRecord(ev_rest, s2);

    // ---- main stream --------------------------------------------------
    embed_kernel<<<ROWS, 256>>>(captions, cap_emb, pos_emb, px, pxh);
    cudaStreamWaitEvent(0, ev_wqkv, 0);   // need packed QKV weights

    for (int i = 0; i < LL; i++) {
        hgemm<false, false, true><<<gQKV, 128, HG2_SMEM>>>(pxh, pwqkvh + (size_t)i * DD * QKVLD,
                                                           nullptr, pqkvh, ROWS, QKVLD, DD);
        flash_attn2<<<NB * HH * 8, 128>>>(pqkvh, pqkvh + DD, pqkvh + 2 * DD, pattnh);
        if (i == 0) cudaStreamWaitEvent(0, ev_rest, 0);   // Wo/W1/W2/Ws + z ready
        hgemm<false, true, true><<<gP, 128, HG2_SMEM>>>(pattnh, pwoh + (size_t)i * DD * DD,
                                                        sa_bo + (size_t)i * DD, pth, ROWS, DD, DD);
        ln_fused2<<<ROWS, 256>>>(px, pth, sa_g + (size_t)i * DD, sa_b + (size_t)i * DD,
                                 pz + (size_t)i * NB * 16 * DD,
                                 ca_g + (size_t)i * DD, ca_b + (size_t)i * DD, px, pxh);

        hgemm<true, true, true><<<gF, 128, HG2_SMEM>>>(pxh, pw1h + (size_t)i * DD * FFD,
                                                       ff_b1 + (size_t)i * FFD, phh, ROWS, FFD, DD);
        hgemm<false, true, true><<<gP, 128, HG2_SMEM>>>(phh, pw2h + (size_t)i * FFD * DD,
                                                        ff_b2 + (size_t)i * DD, pth, ROWS, DD, FFD);
        if (i + 1 < LL)
            ln_kernel<true><<<ROWS, 256>>>(px, pth, ff_g + (size_t)i * DD, ff_b + (size_t)i * DD, px, pxh);
        else
            ln_kernel<false><<<ROWS, 256>>>(px, pth, ff_g + (size_t)i * DD, ff_b + (size_t)i * DD, px, pxh);
    }

    // final vocab projection
    hgemm<false, true, false><<<dim3((VV + 127) / 128, ROWS / 128), 128, HG2_SMEM>>>(
        pxh, pwsh, score_b, out, ROWS, VV, DD);
}

// round 16
// speedup vs baseline: 1.0588x; 1.0588x over previous
#include <cuda_runtime.h>
#include <cuda_bf16.h>
#include <cuda_fp16.h>
#include <cstdio>
#include <cstdint>

// Problem constants
#define NB   16
#define TT   512
#define VV   10000
#define DIN  2048
#define DD   1024
#define HH   16
#define LL   4
#define FFD  2048
#define DHD  64
#define ROWS (NB*TT)          // 8192
#define QKVLD (3*DD)          // 3072

// ---------------- device scratch ----------------
__device__ float g_x[ROWS * DD];
__device__ float g_fe[NB * DD];
__device__ float g_fev[LL * NB * DD];
__device__ float g_ztile[LL * NB * 16 * DD];
__device__ float g_z[LL * NB * 16 * DD];

// fp16 side
__device__ __half g_xh[ROWS * DD];
__device__ __half g_qkvh[ROWS * QKVLD];
__device__ __half g_attnh[ROWS * DD];
__device__ __half g_th[ROWS * DD];
__device__ __half g_hh[ROWS * FFD];
__device__ __half g_wqkvh[LL * DD * QKVLD];
__device__ __half g_woh[LL * DD * DD];
__device__ __half g_w1h[LL * DD * FFD];
__device__ __half g_w2h[LL * FFD * DD];
__device__ __half g_wsh[DD * VV];

// ---------------- small helpers ----------------
__device__ __forceinline__ unsigned h2_as_u32(__half2 h) {
    return *(unsigned*)&h;
}
__device__ __forceinline__ uint32_t smem_u32(const void* p) {
    uint32_t a;
    asm("{ .reg .u64 t; cvta.to.shared.u64 t, %1; cvt.u32.u64 %0, t; }"
        : "=r"(a) : "l"(p));
    return a;
}

#define CPA16(dst, src) \
    asm volatile("cp.async.cg.shared.global [%0], [%1], 16;" :: "r"(dst), "l"(src))
#define CPA16Z(dst, src, sz) \
    asm volatile("cp.async.cg.shared.global [%0], [%1], 16, %2;" :: "r"(dst), "l"(src), "r"(sz))
#define CPA_COMMIT() asm volatile("cp.async.commit_group;" ::: "memory")
#define CPA_WAIT1()  asm volatile("cp.async.wait_group 1;" ::: "memory")
#define CPA_WAIT2()  asm volatile("cp.async.wait_group 2;" ::: "memory")

#define LDSM4(r0, r1, r2, r3, addr) \
    asm volatile("ldmatrix.sync.aligned.m8n8.x4.shared.b16 {%0,%1,%2,%3}, [%4];" \
                 : "=r"(r0), "=r"(r1), "=r"(r2), "=r"(r3) : "r"(addr))
#define LDSM4T(r0, r1, r2, r3, addr) \
    asm volatile("ldmatrix.sync.aligned.m8n8.x4.trans.shared.b16 {%0,%1,%2,%3}, [%4];" \
                 : "=r"(r0), "=r"(r1), "=r"(r2), "=r"(r3) : "r"(addr))

#define MMA16816(acc, a0, a1, a2, a3, b0, b1) \
    asm volatile( \
        "mma.sync.aligned.m16n8k16.row.col.f32.f16.f16.f32 " \
        "{%0,%1,%2,%3}, {%4,%5,%6,%7}, {%8,%9}, {%0,%1,%2,%3};" \
        : "+f"((acc)[0]), "+f"((acc)[1]), "+f"((acc)[2]), "+f"((acc)[3]) \
        : "r"(a0), "r"(a1), "r"(a2), "r"(a3), "r"(b0), "r"(b1))

// warp-shuffle + 8-partial block reduction (256 threads). One barrier.
// Returns (sum, sumsq) in every thread.
__device__ __forceinline__ void block_reduce2(float s, float q, float* w1, float* w2,
                                              int tid, float& outS, float& outQ)
{
#pragma unroll
    for (int o = 16; o > 0; o >>= 1) {
        s += __shfl_xor_sync(0xffffffffu, s, o);
        q += __shfl_xor_sync(0xffffffffu, q, o);
    }
    if ((tid & 31) == 0) { w1[tid >> 5] = s; w2[tid >> 5] = q; }
    __syncthreads();
    float ts = 0.f, tq = 0.f;
#pragma unroll
    for (int i = 0; i < 8; i++) { ts += w1[i]; tq += w2[i]; }
    outS = ts; outQ = tq;
}

// ---------------- f32 -> f16 conversion (n % 4 == 0) ----------------
__global__ void f2h_kernel(const float* __restrict__ src, __half* __restrict__ dst, int n)
{
    int i = (blockIdx.x * blockDim.x + threadIdx.x) * 4;
    if (i < n) {
        float4 v = *(const float4*)(src + i);
        uint2 o;
        o.x = h2_as_u32(__floats2half2_rn(v.x, v.y));
        o.y = h2_as_u32(__floats2half2_rn(v.z, v.w));
        *(uint2*)(dst + i) = o;
    }
}

// pack Wq|Wk|Wv -> [l][k][3*DD] fp16.
__global__ void f2h3_kernel(const float* __restrict__ wq, const float* __restrict__ wk,
                            const float* __restrict__ wv, __half* __restrict__ dst)
{
    const int sel = blockIdx.y;
    const float* src = (sel == 0) ? wq : (sel == 1) ? wk : wv;
    int i = (blockIdx.x * blockDim.x + threadIdx.x) * 4;
    if (i < LL * DD * DD) {
        float4 v = *(const float4*)(src + i);
        const int lk = i >> 10;
        const int j  = i & (DD - 1);
        __half* d = dst + (size_t)lk * QKVLD + sel * DD + j;
        uint2 o;
        o.x = h2_as_u32(__floats2half2_rn(v.x, v.y));
        o.y = h2_as_u32(__floats2half2_rn(v.z, v.w));
        *(uint2*)d = o;
    }
}

// ==== fp16 GEMM: 128x128 CTA tile, 4 warps (2x2, 64x64 each), 4 stages ====
// (round-14 winner, unchanged)
template<bool RELU, bool BIAS, bool HOUT>
__global__ __launch_bounds__(128, 2) void hgemm(
    const __half* __restrict__ A, const __half* __restrict__ B,
    const float* __restrict__ bias, void* __restrict__ Cv,
    int M, int Nn, int K)
{
    __shared__ __align__(16) unsigned char sm[4][16384];

    const int tid  = threadIdx.x;
    const int lane = tid & 31;
    const int warp = tid >> 5;
    const int row0 = blockIdx.y * 128;
    const int col0 = blockIdx.x * 128;
    const int wm = (warp >> 1) * 64;
    const int wn = (warp & 1) * 64;
    const int g  = lane >> 2;
    const int tq = lane & 3;

    const uint32_t sbase = smem_u32(sm);

    int aR[4], aU[4], aPhys[4];
    int bKr[4], bNu[4], bPhys[4];
    unsigned bSz[4];
#pragma unroll
    for (int i = 0; i < 4; i++) {
        const int ul = tid + 128 * i;
        aR[i] = ul >> 2; aU[i] = ul & 3;
        aPhys[i] = aR[i] * 4 + (aU[i] ^ ((aR[i] & 7) >> 1));
        bKr[i] = ul >> 4; bNu[i] = ul & 15;
        bPhys[i] = bKr[i] * 16 + (bNu[i] ^ (bKr[i] & 7));
        bSz[i] = (col0 + bNu[i] * 8 + 7 < Nn) ? 16u : 0u;
    }

    const int g8 = lane >> 3, li = lane & 7;
    const int rowa = wm + (g8 & 1) * 8 + li;
    const int sa = (rowa & 7) >> 1;
    const int ub = g8 >> 1;
    const uint32_t aOff0 = (uint32_t)rowa * 64 + ((unsigned)((0 + ub) ^ sa) << 4);
    const uint32_t aOff1 = (uint32_t)rowa * 64 + ((unsigned)((2 + ub) ^ sa) << 4);
    const int krb = (g8 & 1) * 8 + li;
    const int sb = krb & 7;
    const int nub = (wn >> 3) + (g8 >> 1);
    uint32_t bOff[2][4];
#pragma unroll
    for (int kk = 0; kk < 2; kk++)
#pragma unroll
        for (int jp = 0; jp < 4; jp++)
            bOff[kk][jp] = 8192u + (uint32_t)krb * 256 + (uint32_t)kk * 4096
                         + ((unsigned)((nub + 2 * jp) ^ sb) << 4);

    float acc[4][8][4];
#pragma unroll
    for (int i = 0; i < 4; i++)
#pragma unroll
        for (int j = 0; j < 8; j++)
#pragma unroll
            for (int c = 0; c < 4; c++) acc[i][j][c] = 0.f;

    const int nk = K >> 5;

    auto issue = [&](int c, int st) {
        const int k0 = c * 32;
        const uint32_t stb = sbase + (uint32_t)st * 16384;
#pragma unroll
        for (int i = 0; i < 4; i++) {
            const __half* src = A + (size_t)(row0 + aR[i]) * K + k0 + aU[i] * 8;
            CPA16(stb + (uint32_t)aPhys[i] * 16, src);
        }
#pragma unroll
        for (int i = 0; i < 4; i++) {
            const int gc = col0 + bNu[i] * 8;
            const __half* src = B + (size_t)(k0 + bKr[i]) * Nn + (bSz[i] ? gc : 0);
            CPA16Z(stb + 8192u + (uint32_t)bPhys[i] * 16, src, bSz[i]);
        }
        CPA_COMMIT();
    };

    issue(0, 0);
    issue(1, 1);
    issue(2, 2);

    for (int it = 0; it < nk; it++) {
        const int st = it & 3;
        CPA_WAIT2();
        __syncthreads();
        if (it + 3 < nk) issue(it + 3, (it + 3) & 3);
        else CPA_COMMIT();

        const uint32_t stb = sbase + (uint32_t)st * 16384;
#pragma unroll
        for (int kk = 0; kk < 2; kk++) {
            unsigned af[4][4], bf[8][2];
            const uint32_t aO = (kk == 0) ? aOff0 : aOff1;
#pragma unroll
            for (int i = 0; i < 4; i++)
                LDSM4(af[i][0], af[i][1], af[i][2], af[i][3],
                      stb + aO + (uint32_t)i * 1024);
#pragma unroll
            for (int jp = 0; jp < 4; jp++) {
                unsigned t0, t1, t2, t3;
                LDSM4T(t0, t1, t2, t3, stb + bOff[kk][jp]);
                bf[2 * jp][0] = t0; bf[2 * jp][1] = t1;
                bf[2 * jp + 1][0] = t2; bf[2 * jp + 1][1] = t3;
            }
#pragma unroll
            for (int i = 0; i < 4; i++)
#pragma unroll
                for (int j = 0; j < 8; j++)
                    MMA16816(acc[i][j], af[i][0], af[i][1], af[i][2], af[i][3],
                             bf[j][0], bf[j][1]);
        }
    }

#pragma unroll
    for (int i = 0; i < 4; i++) {
        const int r0r = row0 + wm + i * 16 + g;
#pragma unroll
        for (int j = 0; j < 8; j++) {
            const int col = col0 + wn + j * 8 + tq * 2;
            if (col >= Nn) continue;
            float2 bsv = make_float2(0.f, 0.f);
            if (BIAS) bsv = *(const float2*)(bias + col);
            float2 v0, v1;
            v0.x = acc[i][j][0] + (BIAS ? bsv.x : 0.f);
            v0.y = acc[i][j][1] + (BIAS ? bsv.y : 0.f);
            v1.x = acc[i][j][2] + (BIAS ? bsv.x : 0.f);
            v1.y = acc[i][j][3] + (BIAS ? bsv.y : 0.f);
            if (RELU) {
                v0.x = fmaxf(v0.x, 0.f); v0.y = fmaxf(v0.y, 0.f);
                v1.x = fmaxf(v1.x, 0.f); v1.y = fmaxf(v1.y, 0.f);
            }
            if (HOUT) {
                __half* C = (__half*)Cv;
                *(unsigned*)(C + (size_t)r0r * Nn + col)       = h2_as_u32(__floats2half2_rn(v0.x, v0.y));
                *(unsigned*)(C + (size_t)(r0r + 8) * Nn + col) = h2_as_u32(__floats2half2_rn(v1.x, v1.y));
            } else {
                float* C = (float*)Cv;
                *(float2*)(C + (size_t)r0r * Nn + col) = v0;
                *(float2*)(C + (size_t)(r0r + 8) * Nn + col) = v1;
            }
        }
    }
}

// ---------------- SIMT SGEMM (small M cases only) -------------------------
#define BM 128
#define BN 128
#define BK 8
#define TM 8
#define TN 8

template<bool RELU, bool BIAS>
__global__ void sgemm(const float* __restrict__ A, const float* __restrict__ B,
                      const float* __restrict__ bias, float* __restrict__ C,
                      int M, int Nn, int K)
{
    __shared__ float As[BK][BM];
    __shared__ float Bs[BK][BN];
    const int tid = threadIdx.x;
    const int row0 = blockIdx.y * BM;
    const int col0 = blockIdx.x * BN;
    const int tx = tid % 16;
    const int ty = tid / 16;

    float acc[TM][TN];
#pragma unroll
    for (int i = 0; i < TM; i++)
#pragma unroll
        for (int j = 0; j < TN; j++) acc[i][j] = 0.f;

    const int aRow = tid >> 1;
    const int aCol = (tid & 1) * 4;
    const int bRow = tid >> 5;
    const int bCol = (tid & 31) * 4;

    for (int k0 = 0; k0 < K; k0 += BK) {
        int gr = row0 + aRow;
        float4 av = make_float4(0.f, 0.f, 0.f, 0.f);
        if (gr < M) av = *(const float4*)(A + (size_t)gr * K + k0 + aCol);
        As[aCol + 0][aRow] = av.x;
        As[aCol + 1][aRow] = av.y;
        As[aCol + 2][aRow] = av.z;
        As[aCol + 3][aRow] = av.w;

        int gc = col0 + bCol;
        float4 bv = make_float4(0.f, 0.f, 0.f, 0.f);
        if (gc < Nn) bv = *(const float4*)(B + (size_t)(k0 + bRow) * Nn + gc);
        *(float4*)&Bs[bRow][bCol] = bv;
        __syncthreads();

#pragma unroll
        for (int kk = 0; kk < BK; kk++) {
            float ar[TM], br[TN];
#pragma unroll
            for (int i = 0; i < TM; i++) ar[i] = As[kk][ty * TM + i];
#pragma unroll
            for (int j = 0; j < TN; j++) br[j] = Bs[kk][tx * TN + j];
#pragma unroll
            for (int i = 0; i < TM; i++)
#pragma unroll
                for (int j = 0; j < TN; j++)
                    acc[i][j] = fmaf(ar[i], br[j], acc[i][j]);
        }
        __syncthreads();
    }

#pragma unroll
    for (int i = 0; i < TM; i++) {
        int r = row0 + ty * TM + i;
        if (r >= M) continue;
#pragma unroll
        for (int j = 0; j < TN; j++) {
            int c = col0 + tx * TN + j;
            if (c >= Nn) continue;
            float v = acc[i][j];
            if (BIAS) v += bias[c];
            if (RELU) v = fmaxf(v, 0.f);
            C[(size_t)r * Nn + c] = v;
        }
    }
}

template<bool BIAS>
__global__ void sgemm_bz(const float* __restrict__ A0, const float* __restrict__ B0,
                         const float* __restrict__ bias0, float* __restrict__ C0,
                         int M, int Nn, int K,
                         size_t sA, size_t sB, size_t sBias, size_t sC)
{
    const int z = blockIdx.z;
    const float* A = A0 + sA * z;
    const float* B = B0 + sB * z;
    const float* bias = BIAS ? (bias0 + sBias * z) : nullptr;
    float* C = C0 + sC * z;

    __shared__ float As[BK][BM];
    __shared__ float Bs[BK][BN];
    const int tid = threadIdx.x;
    const int row0 = blockIdx.y * BM;
    const int col0 = blockIdx.x * BN;
    const int tx = tid % 16;
    const int ty = tid / 16;

    float acc[TM][TN];
#pragma unroll
    for (int i = 0; i < TM; i++)
#pragma unroll
        for (int j = 0; j < TN; j++) acc[i][j] = 0.f;

    const int aRow = tid >> 1;
    const int aCol = (tid & 1) * 4;
    const int bRow = tid >> 5;
    const int bCol = (tid & 31) * 4;

    for (int k0 = 0; k0 < K; k0 += BK) {
        int gr = row0 + aRow;
        float4 av = make_float4(0.f, 0.f, 0.f, 0.f);
        if (gr < M) av = *(const float4*)(A + (size_t)gr * K + k0 + aCol);
        As[aCol + 0][aRow] = av.x;
        As[aCol + 1][aRow] = av.y;
        As[aCol + 2][aRow] = av.z;
        As[aCol + 3][aRow] = av.w;

        int gc = col0 + bCol;
        float4 bv = make_float4(0.f, 0.f, 0.f, 0.f);
        if (gc < Nn) bv = *(const float4*)(B + (size_t)(k0 + bRow) * Nn + gc);
        *(float4*)&Bs[bRow][bCol] = bv;
        __syncthreads();

#pragma unroll
        for (int kk = 0; kk < BK; kk++) {
            float ar[TM], br[TN];
#pragma unroll
            for (int i = 0; i < TM; i++) ar[i] = As[kk][ty * TM + i];
#pragma unroll
            for (int j = 0; j < TN; j++) br[j] = Bs[kk][tx * TN + j];
#pragma unroll
            for (int i = 0; i < TM; i++)
#pragma unroll
                for (int j = 0; j < TN; j++)
                    acc[i][j] = fmaf(ar[i], br[j], acc[i][j]);
        }
        __syncthreads();
    }

#pragma unroll
    for (int i = 0; i < TM; i++) {
        int r = row0 + ty * TM + i;
        if (r >= M) continue;
#pragma unroll
        for (int j = 0; j < TN; j++) {
            int c = col0 + tx * TN + j;
            if (c >= Nn) continue;
            float v = acc[i][j];
            if (BIAS) v += bias[c];
            C[(size_t)r * Nn + c] = v;
        }
    }
}

// ---------------- embedding (dual write f32 + f16) ------------
__global__ void embed_kernel(const int* __restrict__ cap, const float* __restrict__ emb,
                             const float* __restrict__ pos, float* __restrict__ X,
                             __half* __restrict__ Xh)
{
    int r = blockIdx.x;
    int t = r & (TT - 1);
    int c = cap[r];
    int d = threadIdx.x * 4;
    float4 e = *(const float4*)(emb + (size_t)c * DD + d);
    float4 p = *(const float4*)(pos + (size_t)t * DD + d);
    e.x += p.x; e.y += p.y; e.z += p.z; e.w += p.w;
    *(float4*)(X + (size_t)r * DD + d) = e;
    uint2 hv;
    hv.x = h2_as_u32(__floats2half2_rn(e.x, e.y));
    hv.y = h2_as_u32(__floats2half2_rn(e.z, e.w));
    *(uint2*)(Xh + (size_t)r * DD + d) = hv;
}

// ============ tensor-core flash attention (packed QKV input) ==============
__global__ __launch_bounds__(128) void flash_attn2(
    const __half* __restrict__ Q, const __half* __restrict__ K,
    const __half* __restrict__ V, __half* __restrict__ O)
{
    __shared__ __align__(16) unsigned char sQ[8192];
    __shared__ __align__(16) unsigned char sKV[2][16384];

    const int bid = blockIdx.x;
    const int qt = bid & 7;
    const int h  = (bid >> 3) & 15;
    const int n  = bid >> 7;
    const int q0 = qt * 64;

    const int tid = threadIdx.x;
    const int lane = tid & 31;
    const int warp = tid >> 5;
    const int g8 = lane >> 3, li = lane & 7;
    const int g = lane >> 2, tq = lane & 3;

    const uint32_t sQb = smem_u32(sQ);
    const uint32_t sKVb = smem_u32(sKV);

#pragma unroll
    for (int i = 0; i < 4; i++) {
        const int ui = tid + 128 * i;
        const int r = ui >> 3, u = ui & 7;
        const int phys = r * 8 + (u ^ (r & 7));
        CPA16(sQb + phys * 16,
              Q + ((size_t)(n * TT + q0 + r)) * QKVLD + h * DHD + u * 8);
    }
    CPA_COMMIT();

    auto load_kv = [&](int t, int buf) {
        const int j0 = t * 64;
        const uint32_t base = sKVb + (uint32_t)buf * 16384;
#pragma unroll
        for (int i = 0; i < 4; i++) {
            const int ui = tid + 128 * i;
            const int r = ui >> 3, u = ui & 7;
            const int phys = r * 8 + (u ^ (r & 7));
            const size_t go = ((size_t)(n * TT + j0 + r)) * QKVLD + h * DHD + u * 8;
            CPA16(base + phys * 16, K + go);
            CPA16(base + 8192u + phys * 16, V + go);
        }
        CPA_COMMIT();
    };

    load_kv(0, 0);
    CPA_WAIT1();
    __syncthreads();

    unsigned qa[4][4];
    {
        const int qrow = 16 * warp + (g8 & 1) * 8 + li;
#pragma unroll
        for (int kc = 0; kc < 4; kc++) {
            const int u = 2 * kc + (g8 >> 1);
            LDSM4(qa[kc][0], qa[kc][1], qa[kc][2], qa[kc][3],
                  sQb + (uint32_t)(qrow * 8 + (u ^ (qrow & 7))) * 16);
        }
    }

    float o[8][4];
#pragma unroll
    for (int j = 0; j < 8; j++)
#pragma unroll
        for (int c = 0; c < 4; c++) o[j][c] = 0.f;
    float m0 = -1e30f, m1 = -1e30f, l0 = 0.f, l1 = 0.f;

    const int r0q = q0 + 16 * warp + g;
    const int nt = qt + 1;

    const int kbrow = (g8 >> 1) * 8 + li;
    const int vrow  = (g8 & 1) * 8 + li;

    for (int t = 0; t < nt; t++) {
        const int buf = t & 1;
        __syncthreads();
        if (t + 1 < nt) load_kv(t + 1, buf ^ 1);
        else CPA_COMMIT();
        CPA_WAIT1();
        __syncthreads();

        const uint32_t kb = sKVb + (uint32_t)buf * 16384;
        const uint32_t vb = kb + 8192u;

        float s[8][4];
#pragma unroll
        for (int j = 0; j < 8; j++)
#pragma unroll
            for (int c = 0; c < 4; c++) s[j][c] = 0.f;

#pragma unroll
        for (int kc = 0; kc < 4; kc++) {
            const int ku = 2 * kc + (g8 & 1);
#pragma unroll
            for (int jp = 0; jp < 4; jp++) {
                const int row = 16 * jp + kbrow;
                unsigned t0, t1, t2, t3;
                LDSM4(t0, t1, t2, t3,
                      kb + (uint32_t)(row * 8 + (ku ^ (row & 7))) * 16);
                MMA16816(s[2 * jp],     qa[kc][0], qa[kc][1], qa[kc][2], qa[kc][3], t0, t1);
                MMA16816(s[2 * jp + 1], qa[kc][0], qa[kc][1], qa[kc][2], qa[kc][3], t2, t3);
            }
        }

        const int j0 = t * 64;
        float mx0 = -1e30f, mx1 = -1e30f;
        if (t == qt) {
#pragma unroll
            for (int j = 0; j < 8; j++) {
                const int col = j0 + 8 * j + 2 * tq;
                s[j][0] = (col     <= r0q)     ? s[j][0] * 0.125f : -1e30f;
                s[j][1] = (col + 1 <= r0q)     ? s[j][1] * 0.125f : -1e30f;
                s[j][2] = (col     <= r0q + 8) ? s[j][2] * 0.125f : -1e30f;
                s[j][3] = (col + 1 <= r0q + 8) ? s[j][3] * 0.125f : -1e30f;
                mx0 = fmaxf(mx0, fmaxf(s[j][0], s[j][1]));
                mx1 = fmaxf(mx1, fmaxf(s[j][2], s[j][3]));
            }
        } else {
#pragma unroll
            for (int j = 0; j < 8; j++) {
                s[j][0] *= 0.125f; s[j][1] *= 0.125f;
                s[j][2] *= 0.125f; s[j][3] *= 0.125f;
                mx0 = fmaxf(mx0, fmaxf(s[j][0], s[j][1]));
                mx1 = fmaxf(mx1, fmaxf(s[j][2], s[j][3]));
            }
        }
        mx0 = fmaxf(mx0, __shfl_xor_sync(0xffffffffu, mx0, 1));
        mx0 = fmaxf(mx0, __shfl_xor_sync(0xffffffffu, mx0, 2));
        mx1 = fmaxf(mx1, __shfl_xor_sync(0xffffffffu, mx1, 1));
        mx1 = fmaxf(mx1, __shfl_xor_sync(0xffffffffu, mx1, 2));

        const float mn0 = fmaxf(m0, mx0);
        const float mn1 = fmaxf(m1, mx1);
        const float sc0 = __expf(m0 - mn0);
        const float sc1 = __expf(m1 - mn1);
        m0 = mn0; m1 = mn1;
        l0 *= sc0; l1 *= sc1;
#pragma unroll
        for (int j = 0; j < 8; j++) {
            o[j][0] *= sc0; o[j][1] *= sc0;
            o[j][2] *= sc1; o[j][3] *= sc1;
        }

        unsigned pa[8], pb[8];
#pragma unroll
        for (int j = 0; j < 8; j++) {
            const float p0 = __expf(s[j][0] - mn0);
            const float p1 = __expf(s[j][1] - mn0);
            const float p2 = __expf(s[j][2] - mn1);
            const float p3 = __expf(s[j][3] - mn1);
            l0 += p0 + p1; l1 += p2 + p3;
            pa[j] = h2_as_u32(__floats2half2_rn(p0, p1));
            pb[j] = h2_as_u32(__floats2half2_rn(p2, p3));
        }

#pragma unroll
        for (int kc = 0; kc < 4; kc++) {
#pragma unroll
            for (int jp = 0; jp < 4; jp++) {
                const int row = 16 * kc + vrow;
                const int u = 2 * jp + (g8 >> 1);
                unsigned t0, t1, t2, t3;
                LDSM4T(t0, t1, t2, t3,
                       vb + (uint32_t)(row * 8 + (u ^ (row & 7))) * 16);
                MMA16816(o[2 * jp],     pa[2 * kc], pb[2 * kc], pa[2 * kc + 1], pb[2 * kc + 1], t0, t1);
                MMA16816(o[2 * jp + 1], pa[2 * kc], pb[2 * kc], pa[2 * kc + 1], pb[2 * kc + 1], t2, t3);
            }
        }
    }

    l0 += __shfl_xor_sync(0xffffffffu, l0, 1);
    l0 += __shfl_xor_sync(0xffffffffu, l0, 2);
    l1 += __shfl_xor_sync(0xffffffffu, l1, 1);
    l1 += __shfl_xor_sync(0xffffffffu, l1, 2);
    const float inv0 = 1.f / l0;
    const float inv1 = 1.f / l1;

    const size_t obase = ((size_t)((n * HH + h) * TT + q0 + 16 * warp)) * DHD;
#pragma unroll
    for (int j = 0; j < 8; j++) {
        const int col = 8 * j + 2 * tq;
        *(unsigned*)(O + obase + (size_t)g * DHD + col) =
            h2_as_u32(__floats2half2_rn(o[j][0] * inv0, o[j][1] * inv0));
        *(unsigned*)(O + obase + (size_t)(g + 8) * DHD + col) =
            h2_as_u32(__floats2half2_rn(o[j][2] * inv1, o[j][3] * inv1));
    }
}

// ---------------- residual + LayerNorm (fp16 delta, dual write) ----------
template<bool FOUT>
__global__ void ln_kernel(const float* __restrict__ X, const __half* __restrict__ Dd,
                          const float* __restrict__ g, const float* __restrict__ b,
                          float* __restrict__ out, __half* __restrict__ outh)
{
    const int r = blockIdx.x;
    const int tid = threadIdx.x;
    const int d = tid * 4;
    float4 xv = *(const float4*)(X + (size_t)r * DD + d);
    uint2 du = *(const uint2*)(Dd + (size_t)r * DD + d);
    float2 d0 = __half22float2(*(__half2*)&du.x);
    float2 d1 = __half22float2(*(__half2*)&du.y);
    float v0 = xv.x + d0.x, v1 = xv.y + d0.y, v2 = xv.z + d1.x, v3 = xv.w + d1.y;

    __shared__ float w1[8], w2[8];
    float S, Q;
    block_reduce2(v0 + v1 + v2 + v3,
                  v0 * v0 + v1 * v1 + v2 * v2 + v3 * v3, w1, w2, tid, S, Q);
    const float mean = S * (1.f / DD);
    const float var = Q * (1.f / DD) - mean * mean;
    const float rstd = rsqrtf(var + 1e-5f);

    float4 ov;
    ov.x = g[d + 0] * (v0 - mean) * rstd + b[d + 0];
    ov.y = g[d + 1] * (v1 - mean) * rstd + b[d + 1];
    ov.z = g[d + 2] * (v2 - mean) * rstd + b[d + 2];
    ov.w = g[d + 3] * (v3 - mean) * rstd + b[d + 3];
    if (FOUT) *(float4*)(out + (size_t)r * DD + d) = ov;
    uint2 hv;
    hv.x = h2_as_u32(__floats2half2_rn(ov.x, ov.y));
    hv.y = h2_as_u32(__floats2half2_rn(ov.z, ov.w));
    *(uint2*)(outh + (size_t)r * DD + d) = hv;
}

// ---- fused: LN(x + attn_delta) then LN(o1 + z_broadcast) ----------------
__global__ void ln_fused2(const float* __restrict__ X, const __half* __restrict__ Dd,
                          const float* __restrict__ g1, const float* __restrict__ b1,
                          const float* __restrict__ Z,
                          const float* __restrict__ g2, const float* __restrict__ b2,
                          float* __restrict__ out, __half* __restrict__ outh)
{
    const int r = blockIdx.x;
    const int tid = threadIdx.x;
    const int d = tid * 4;
    __shared__ float w1[8], w2[8];

    float4 xv = *(const float4*)(X + (size_t)r * DD + d);
    uint2 du = *(const uint2*)(Dd + (size_t)r * DD + d);
    float2 d0 = __half22float2(*(__half2*)&du.x);
    float2 d1 = __half22float2(*(__half2*)&du.y);
    float v0 = xv.x + d0.x, v1 = xv.y + d0.y, v2 = xv.z + d1.x, v3 = xv.w + d1.y;

    float S, Q;
    block_reduce2(v0 + v1 + v2 + v3,
                  v0 * v0 + v1 * v1 + v2 * v2 + v3 * v3, w1, w2, tid, S, Q);
    float mean = S * (1.f / DD);
    float var = Q * (1.f / DD) - mean * mean;
    float rstd = rsqrtf(var + 1e-5f);

    float o0 = g1[d + 0] * (v0 - mean) * rstd + b1[d + 0];
    float o1_ = g1[d + 1] * (v1 - mean) * rstd + b1[d + 1];
    float o2_ = g1[d + 2] * (v2 - mean) * rstd + b1[d + 2];
    float o3 = g1[d + 3] * (v3 - mean) * rstd + b1[d + 3];

    const int n = r >> 9;
    const int s = r & (TT - 1);
    const size_t zr = (size_t)(n * 16 + (s >> 5));
    float4 zv = *(const float4*)(Z + zr * DD + d);
    v0 = o0 + zv.x; v1 = o1_ + zv.y; v2 = o2_ + zv.z; v3 = o3 + zv.w;

    __syncthreads();   // protect w1/w2 reuse
    block_reduce2(v0 + v1 + v2 + v3,
                  v0 * v0 + v1 * v1 + v2 * v2 + v3 * v3, w1, w2, tid, S, Q);
    mean = S * (1.f / DD);
    var = Q * (1.f / DD) - mean * mean;
    rstd = rsqrtf(var + 1e-5f);

    float4 ov;
    ov.x = g2[d + 0] * (v0 - mean) * rstd + b2[d + 0];
    ov.y = g2[d + 1] * (v1 - mean) * rstd + b2[d + 1];
    ov.z = g2[d + 2] * (v2 - mean) * rstd + b2[d + 2];
    ov.w = g2[d + 3] * (v3 - mean) * rstd + b2[d + 3];
    *(float4*)(out + (size_t)r * DD + d) = ov;
    uint2 hv;
    hv.x = h2_as_u32(__floats2half2_rn(ov.x, ov.y));
    hv.y = h2_as_u32(__floats2half2_rn(ov.z, ov.w));
    *(uint2*)(outh + (size_t)r * DD + d) = hv;
}

// ------------- tiled rows for cross-attn out-projection (batched) --------
__global__ void tilefe_kernel(const float* __restrict__ fev, float* __restrict__ A)
{
    const int bx = blockIdx.x;
    const int z = bx >> 8;
    const int rl = bx & 255;
    const int n = rl >> 4;
    const int g = rl & 15;
    const int d = threadIdx.x * 4;
    const float* src = fev + (size_t)z * NB * DD + (size_t)n * DD + g * 64;
    float4 v = *(const float4*)(src + (d & 63));
    *(float4*)(A + (size_t)z * NB * 16 * DD + (size_t)rl * DD + d) = v;
}

// ---------------- launch --------------------------------------------------
extern "C" void kernel_launch(void* const* d_in, const int* in_sizes, int n_in,
                              void* d_out, int out_size)
{
    const float* features = (const float*)d_in[0];
    const int*   captions = (const int*)d_in[1];
    const float* feat_W   = (const float*)d_in[2];
    const float* feat_b   = (const float*)d_in[3];
    const float* cap_emb  = (const float*)d_in[4];
    const float* pos_emb  = (const float*)d_in[5];
    const float* sa_Wq = (const float*)d_in[6];
    const float* sa_Wk = (const float*)d_in[7];
    const float* sa_Wv = (const float*)d_in[8];
    const float* sa_Wo = (const float*)d_in[9];
    const float* sa_bo = (const float*)d_in[10];
    const float* sa_g  = (const float*)d_in[11];
    const float* sa_b  = (const float*)d_in[12];
    const float* ca_Wv = (const float*)d_in[15];
    const float* ca_Wo = (const float*)d_in[16];
    const float* ca_bo = (const float*)d_in[17];
    const float* ca_g  = (const float*)d_in[18];
    const float* ca_b  = (const float*)d_in[19];
    const float* ff_W1 = (const float*)d_in[20];
    const float* ff_b1 = (const float*)d_in[21];
    const float* ff_W2 = (const float*)d_in[22];
    const float* ff_b2 = (const float*)d_in[23];
    const float* ff_g  = (const float*)d_in[24];
    const float* ff_b  = (const float*)d_in[25];
    const float* score_W = (const float*)d_in[26];
    const float* score_b = (const float*)d_in[27];
    float* out = (float*)d_out;

    float *px, *pfe, *pfev, *pzt, *pz;
    __half *pxh, *pqkvh, *pattnh, *pth, *phh;
    __half *pwqkvh, *pwoh, *pw1h, *pw2h, *pwsh;
    cudaGetSymbolAddress((void**)&px,    g_x);
    cudaGetSymbolAddress((void**)&pfe,   g_fe);
    cudaGetSymbolAddress((void**)&pfev,  g_fev);
    cudaGetSymbolAddress((void**)&pzt,   g_ztile);
    cudaGetSymbolAddress((void**)&pz,    g_z);
    cudaGetSymbolAddress((void**)&pxh,    g_xh);
    cudaGetSymbolAddress((void**)&pqkvh,  g_qkvh);
    cudaGetSymbolAddress((void**)&pattnh, g_attnh);
    cudaGetSymbolAddress((void**)&pth,    g_th);
    cudaGetSymbolAddress((void**)&phh,    g_hh);
    cudaGetSymbolAddress((void**)&pwqkvh, g_wqkvh);
    cudaGetSymbolAddress((void**)&pwoh,   g_woh);
    cudaGetSymbolAddress((void**)&pw1h,   g_w1h);
    cudaGetSymbolAddress((void**)&pw2h,   g_w2h);
    cudaGetSymbolAddress((void**)&pwsh,   g_wsh);

    // side stream + events (created once; first call is eager)
    static cudaStream_t s2 = nullptr;
    static cudaEvent_t ev_fork = nullptr, ev_wqkv = nullptr, ev_rest = nullptr;
    if (!s2) {
        cudaStreamCreateWithFlags(&s2, cudaStreamNonBlocking);
        cudaEventCreateWithFlags(&ev_fork, cudaEventDisableTiming);
        cudaEventCreateWithFlags(&ev_wqkv, cudaEventDisableTiming);
        cudaEventCreateWithFlags(&ev_rest, cudaEventDisableTiming);
    }

    const int tb = 256;
    const int nDD = LL * DD * DD;
    const int nFF = LL * DD * FFD;
    const int nS = DD * VV;

    const dim3 gP(DD / 128, ROWS / 128);        // 8 x 64
    const dim3 gQKV(QKVLD / 128, ROWS / 128);   // 24 x 64
    const dim3 gF(FFD / 128, ROWS / 128);       // 16 x 64

    // ---- fork: prologue on side stream -------------------------------
    cudaEventRecord(ev_fork, 0);
    cudaStreamWaitEvent(s2, ev_fork, 0);

    f2h3_kernel<<<dim3(nDD / 4 / tb, 3), tb, 0, s2>>>(sa_Wq, sa_Wk, sa_Wv, pwqkvh);
    cudaEventRecord(ev_wqkv, s2);
    f2h_kernel<<<(nDD / 4 + tb - 1) / tb, tb, 0, s2>>>(sa_Wo, pwoh, nDD);
    f2h_kernel<<<(nFF / 4 + tb - 1) / tb, tb, 0, s2>>>(ff_W1, pw1h, nFF);
    f2h_kernel<<<(nFF / 4 + tb - 1) / tb, tb, 0, s2>>>(ff_W2, pw2h, nFF);
    f2h_kernel<<<(nS / 4 + tb - 1) / tb, tb, 0, s2>>>(score_W, pwsh, nS);
    sgemm<false, true><<<dim3(DD / BN, 1), 256, 0, s2>>>(features, feat_W, feat_b, pfe, NB, DD, DIN);
    sgemm_bz<false><<<dim3(DD / BN, 1, LL), 256, 0, s2>>>(pfe, ca_Wv, nullptr, pfev,
                                                          NB, DD, DD,
                                                          0, (size_t)DD * DD, 0, (size_t)NB * DD);
    tilefe_kernel<<<LL * NB * 16, 256, 0, s2>>>(pfev, pzt);
    sgemm_bz<true><<<dim3(DD / BN, 2, LL), 256, 0, s2>>>(pzt, ca_Wo, ca_bo, pz,
                                                         NB * 16, DD, DD,
                                                         (size_t)NB * 16 * DD, (size_t)DD * DD,
                                                         DD, (size_t)NB * 16 * DD);
    cudaEventRecord(ev_rest, s2);

    // ---- main stream --------------------------------------------------
    embed_kernel<<<ROWS, 256>>>(captions, cap_emb, pos_emb, px, pxh);
    cudaStreamWaitEvent(0, ev_wqkv, 0);   // need packed QKV weights

    for (int i = 0; i < LL; i++) {
        hgemm<false, false, true><<<gQKV, 128>>>(pxh, pwqkvh + (size_t)i * DD * QKVLD,
                                                 nullptr, pqkvh, ROWS, QKVLD, DD);
        flash_attn2<<<NB * HH * 8, 128>>>(pqkvh, pqkvh + DD, pqkvh + 2 * DD, pattnh);
        if (i == 0) cudaStreamWaitEvent(0, ev_rest, 0);   // Wo/W1/W2/Ws + z ready
        hgemm<false, true, true><<<gP, 128>>>(pattnh, pwoh + (size_t)i * DD * DD,
                                              sa_bo + (size_t)i * DD, pth, ROWS, DD, DD);
        ln_fused2<<<ROWS, 256>>>(px, pth, sa_g + (size_t)i * DD, sa_b + (size_t)i * DD,
                                 pz + (size_t)i * NB * 16 * DD,
                                 ca_g + (size_t)i * DD, ca_b + (size_t)i * DD, px, pxh);

        hgemm<true, true, true><<<gF, 128>>>(pxh, pw1h + (size_t)i * DD * FFD,
                                             ff_b1 + (size_t)i * FFD, phh, ROWS, FFD, DD);
        hgemm<false, true, true><<<gP, 128>>>(phh, pw2h + (size_t)i * FFD * DD,
                                              ff_b2 + (size_t)i * DD, pth, ROWS, DD, FFD);
        if (i + 1 < LL)
            ln_kernel<true><<<ROWS, 256>>>(px, pth, ff_g + (size_t)i * DD, ff_b + (size_t)i * DD, px, pxh);
        else
            ln_kernel<false><<<ROWS, 256>>>(px, pth, ff_g + (size_t)i * DD, ff_b + (size_t)i * DD, px, pxh);
    }

    // final vocab projection
    hgemm<false, true, false><<<dim3((VV + 127) / 128, ROWS / 128), 128>>>(
        pxh, pwsh, score_b, out, ROWS, VV, DD);
}